// round 8
// baseline (speedup 1.0000x reference)
#include <cuda_runtime.h>
#include <cuda_fp16.h>

#define N_NODES 50000
#define N_EDGES 800000
#define D 128

// ---- scratch (device globals; no allocation allowed) ----
__device__ __half g_xsh[N_NODES * D];   // 12.8 MB: (h @ W) * dinv[row], fp16
__device__ float  g_h  [N_NODES * D];   // 25.6 MB: layer-1 output (fp32)
__device__ float  g_dinv[N_NODES];
__device__ int    g_deg [N_NODES];
__device__ int    g_off [N_NODES + 1];
__device__ int    g_cur [N_NODES];
__device__ int    g_csr [N_EDGES];      // source node per incoming edge, grouped by target

// ---------------------------------------------------------------------------
// Histogram of in-degrees, 4 edges per thread (N_EDGES % 4 == 0).
__global__ void k_hist(const int4* __restrict__ col4) {
    int i = blockIdx.x * blockDim.x + threadIdx.x;
    if (i < N_EDGES / 4) {
        int4 c = __ldg(&col4[i]);
        atomicAdd(&g_deg[c.x], 1);
        atomicAdd(&g_deg[c.y], 1);
        atomicAdd(&g_deg[c.z], 1);
        atomicAdd(&g_deg[c.w], 1);
    }
}

// Single-block exclusive scan over 50000 degrees + dinv computation.
__global__ void k_scan() {
    __shared__ int part[1024];
    const int CH = (N_NODES + 1023) / 1024;   // 49
    int t  = threadIdx.x;
    int s0 = t * CH;
    int s1 = min(s0 + CH, N_NODES);

    int sum = 0;
    for (int i = s0; i < s1; i++) sum += g_deg[i];
    part[t] = sum;
    __syncthreads();

    for (int d2 = 1; d2 < 1024; d2 <<= 1) {
        int v = 0;
        if (t >= d2) v = part[t - d2];
        __syncthreads();
        if (t >= d2) part[t] += v;
        __syncthreads();
    }

    int run = (t > 0) ? part[t - 1] : 0;
    for (int i = s0; i < s1; i++) {
        g_off[i] = run;
        g_cur[i] = run;
        int dg = g_deg[i];
        g_dinv[i] = rsqrtf((float)(dg + 1));   // +1 self loop -> always > 0
        run += dg;
    }
    if (t == 1023) g_off[N_NODES] = part[1023];
}

__global__ void k_build_csr(const int4* __restrict__ row4, const int4* __restrict__ col4) {
    int i = blockIdx.x * blockDim.x + threadIdx.x;
    if (i < N_EDGES / 4) {
        int4 r = __ldg(&row4[i]);
        int4 c = __ldg(&col4[i]);
        g_csr[atomicAdd(&g_cur[c.x], 1)] = r.x;
        g_csr[atomicAdd(&g_cur[c.y], 1)] = r.y;
        g_csr[atomicAdd(&g_cur[c.z], 1)] = r.z;
        g_csr[atomicAdd(&g_cur[c.w], 1)] = r.w;
    }
}

// ---------------------------------------------------------------------------
// GEMM: out_h[i,:] = fp16( (A[i,:] @ W) * dinv[i] ).  Block = 128x128,
// 256 threads, each thread 8x8 outputs, K tiled by 16.
__global__ void __launch_bounds__(256, 2)
k_gemm_scale(const float* __restrict__ A, const float* __restrict__ W,
             __half* __restrict__ out) {
    __shared__ float As[128][17];   // +1 pad: conflict-free column reads
    __shared__ float Ws[16][128];

    const int tid = threadIdx.x;
    const int tx  = tid & 15;
    const int ty  = tid >> 4;
    const int rowBase = blockIdx.x * 128;

    float acc[8][8];
#pragma unroll
    for (int i = 0; i < 8; i++)
#pragma unroll
        for (int j = 0; j < 8; j++) acc[i][j] = 0.f;

    for (int k0 = 0; k0 < D; k0 += 16) {
        {
            int r = tid >> 1;
            int h = (tid & 1) * 8;
            int grow = rowBase + r;
            float4 v0 = make_float4(0, 0, 0, 0), v1 = make_float4(0, 0, 0, 0);
            if (grow < N_NODES) {
                v0 = *(const float4*)&A[(size_t)grow * D + k0 + h];
                v1 = *(const float4*)&A[(size_t)grow * D + k0 + h + 4];
            }
            As[r][h + 0] = v0.x; As[r][h + 1] = v0.y; As[r][h + 2] = v0.z; As[r][h + 3] = v0.w;
            As[r][h + 4] = v1.x; As[r][h + 5] = v1.y; As[r][h + 6] = v1.z; As[r][h + 7] = v1.w;
        }
        {
            int wr = tid >> 4;
            int wc = (tid & 15) * 8;
            float4 v0 = *(const float4*)&W[(size_t)(k0 + wr) * D + wc];
            float4 v1 = *(const float4*)&W[(size_t)(k0 + wr) * D + wc + 4];
            *(float4*)&Ws[wr][wc]     = v0;
            *(float4*)&Ws[wr][wc + 4] = v1;
        }
        __syncthreads();

#pragma unroll
        for (int kk = 0; kk < 16; kk++) {
            float a[8], w[8];
#pragma unroll
            for (int i = 0; i < 8; i++) a[i] = As[ty * 8 + i][kk];
            float4 w0 = *(float4*)&Ws[kk][tx * 8];
            float4 w1 = *(float4*)&Ws[kk][tx * 8 + 4];
            w[0] = w0.x; w[1] = w0.y; w[2] = w0.z; w[3] = w0.w;
            w[4] = w1.x; w[5] = w1.y; w[6] = w1.z; w[7] = w1.w;
#pragma unroll
            for (int i = 0; i < 8; i++)
#pragma unroll
                for (int j = 0; j < 8; j++) acc[i][j] = fmaf(a[i], w[j], acc[i][j]);
        }
        __syncthreads();
    }

#pragma unroll
    for (int i = 0; i < 8; i++) {
        int grow = rowBase + ty * 8 + i;
        if (grow < N_NODES) {
            float di = g_dinv[grow];
            union { __half2 h2[4]; uint4 u; } pk;
            pk.h2[0] = __floats2half2_rn(acc[i][0] * di, acc[i][1] * di);
            pk.h2[1] = __floats2half2_rn(acc[i][2] * di, acc[i][3] * di);
            pk.h2[2] = __floats2half2_rn(acc[i][4] * di, acc[i][5] * di);
            pk.h2[3] = __floats2half2_rn(acc[i][6] * di, acc[i][7] * di);
            *(uint4*)&out[(size_t)grow * D + tx * 8] = pk.u;
        }
    }
}

// ---------------------------------------------------------------------------
// Load 4 consecutive fp16 features of row r at half-offset c4, as float4.
__device__ __forceinline__ float4 ld_row4(const __half* __restrict__ xs, int r, int c4) {
    uint2 u = __ldg((const uint2*)(xs + (size_t)r * D + c4));
    __half2 h0 = *(__half2*)&u.x;
    __half2 h1 = *(__half2*)&u.y;
    float2 a0 = __half22float2(h0);
    float2 a1 = __half22float2(h1);
    return make_float4(a0.x, a0.y, a1.x, a1.y);
}

// Gather: one warp per node, fp32 accumulation over fp16 messages.
// out[c] = prelu( dinv[c] * (xs[c] + sum_{incoming e} xs[src(e)]) + b , a )
__global__ void k_gather(const __half* __restrict__ xs, const float* __restrict__ b,
                         const float* __restrict__ a, float* __restrict__ out) {
    int node = (blockIdx.x * blockDim.x + threadIdx.x) >> 5;
    int lane = threadIdx.x & 31;
    if (node >= N_NODES) return;
    const int c4 = lane * 4;

    float4 acc = ld_row4(xs, node, c4);   // self loop

    int s = g_off[node];
    int e = g_off[node + 1];
    int i = s;
    // unroll by 4: four independent load chains in flight
    for (; i + 4 <= e; i += 4) {
        int r0 = __ldg(&g_csr[i]);
        int r1 = __ldg(&g_csr[i + 1]);
        int r2 = __ldg(&g_csr[i + 2]);
        int r3 = __ldg(&g_csr[i + 3]);
        float4 v0 = ld_row4(xs, r0, c4);
        float4 v1 = ld_row4(xs, r1, c4);
        float4 v2 = ld_row4(xs, r2, c4);
        float4 v3 = ld_row4(xs, r3, c4);
        acc.x += (v0.x + v1.x) + (v2.x + v3.x);
        acc.y += (v0.y + v1.y) + (v2.y + v3.y);
        acc.z += (v0.z + v1.z) + (v2.z + v3.z);
        acc.w += (v0.w + v1.w) + (v2.w + v3.w);
    }
    for (; i < e; i++) {
        int r0 = __ldg(&g_csr[i]);
        float4 v0 = ld_row4(xs, r0, c4);
        acc.x += v0.x; acc.y += v0.y; acc.z += v0.z; acc.w += v0.w;
    }

    float  di = g_dinv[node];
    float4 bb = *(const float4*)&b[c4];
    float4 aa = *(const float4*)&a[c4];
    float4 o;
    o.x = fmaf(di, acc.x, bb.x); o.x = (o.x >= 0.f) ? o.x : aa.x * o.x;
    o.y = fmaf(di, acc.y, bb.y); o.y = (o.y >= 0.f) ? o.y : aa.y * o.y;
    o.z = fmaf(di, acc.z, bb.z); o.z = (o.z >= 0.f) ? o.z : aa.z * o.z;
    o.w = fmaf(di, acc.w, bb.w); o.w = (o.w >= 0.f) ? o.w : aa.w * o.w;
    *(float4*)&out[(size_t)node * D + c4] = o;
}

// ---------------------------------------------------------------------------
extern "C" void kernel_launch(void* const* d_in, const int* in_sizes, int n_in,
                              void* d_out, int out_size) {
    const float* x  = (const float*)d_in[0];
    const int*   ei = (const int*)  d_in[1];
    const float* W1 = (const float*)d_in[2];
    const float* b1 = (const float*)d_in[3];
    const float* a1 = (const float*)d_in[4];
    const float* W2 = (const float*)d_in[5];
    const float* b2 = (const float*)d_in[6];
    const float* a2 = (const float*)d_in[7];
    float* out = (float*)d_out;

    const int4* row4 = (const int4*)ei;               // edge_index[0] = sources
    const int4* col4 = (const int4*)(ei + N_EDGES);   // edge_index[1] = targets

    __half *xs_ptr;  float *h_ptr;  int *deg_ptr;
    cudaGetSymbolAddress((void**)&xs_ptr,  g_xsh);
    cudaGetSymbolAddress((void**)&h_ptr,   g_h);
    cudaGetSymbolAddress((void**)&deg_ptr, g_deg);

    // CSR build (once; reused by both layers)
    cudaMemsetAsync(deg_ptr, 0, N_NODES * sizeof(int), 0);
    const int e4blocks = (N_EDGES / 4 + 255) / 256;
    k_hist     <<<e4blocks, 256>>>(col4);
    k_scan     <<<1, 1024>>>();
    k_build_csr<<<e4blocks, 256>>>(row4, col4);

    const int gemm_blocks   = (N_NODES + 127) / 128;
    const int gather_blocks = (N_NODES * 32 + 255) / 256;

    // layer 1
    k_gemm_scale<<<gemm_blocks, 256>>>(x, W1, xs_ptr);
    k_gather   <<<gather_blocks, 256>>>(xs_ptr, b1, a1, h_ptr);
    // layer 2
    k_gemm_scale<<<gemm_blocks, 256>>>(h_ptr, W2, xs_ptr);
    k_gather   <<<gather_blocks, 256>>>(xs_ptr, b2, a2, out);
}

// round 9
// speedup vs baseline: 1.1889x; 1.1889x over previous
#include <cuda_runtime.h>
#include <cuda_fp16.h>
#include <mma.h>

using namespace nvcuda;

#define N_NODES 50000
#define N_EDGES 800000
#define D 128
#define N_PAD 50048              // 782 * 64, padded row count for guard-free GEMM

// ---- scratch (device globals; no allocation allowed) ----
__device__ __half g_a  [N_PAD * D];     // 12.8 MB: GEMM input, rows pre-scaled by dinv
__device__ __half g_xsh[N_PAD * D];     // 12.8 MB: GEMM output = messages (fp16)
__device__ __half g_w1 [D * D];
__device__ __half g_w2 [D * D];
__device__ float  g_dinv[N_NODES];
__device__ int    g_deg [N_NODES];
__device__ int    g_off [N_NODES + 1];
__device__ int    g_cur [N_NODES];
__device__ int    g_csr [N_EDGES];      // source node per incoming edge, grouped by target

// ---------------------------------------------------------------------------
__global__ void k_hist(const int4* __restrict__ col4) {
    int i = blockIdx.x * blockDim.x + threadIdx.x;
    if (i < N_EDGES / 4) {
        int4 c = __ldg(&col4[i]);
        atomicAdd(&g_deg[c.x], 1);
        atomicAdd(&g_deg[c.y], 1);
        atomicAdd(&g_deg[c.z], 1);
        atomicAdd(&g_deg[c.w], 1);
    }
}

// Single-block exclusive scan over 50000 degrees + dinv computation.
__global__ void k_scan() {
    __shared__ int part[1024];
    const int CH = (N_NODES + 1023) / 1024;   // 49
    int t  = threadIdx.x;
    int s0 = t * CH;
    int s1 = min(s0 + CH, N_NODES);

    int sum = 0;
    for (int i = s0; i < s1; i++) sum += g_deg[i];
    part[t] = sum;
    __syncthreads();

    for (int d2 = 1; d2 < 1024; d2 <<= 1) {
        int v = 0;
        if (t >= d2) v = part[t - d2];
        __syncthreads();
        if (t >= d2) part[t] += v;
        __syncthreads();
    }

    int run = (t > 0) ? part[t - 1] : 0;
    for (int i = s0; i < s1; i++) {
        g_off[i] = run;
        g_cur[i] = run;
        int dg = g_deg[i];
        g_dinv[i] = rsqrtf((float)(dg + 1));   // +1 self loop -> always > 0
        run += dg;
    }
    if (t == 1023) g_off[N_NODES] = part[1023];
}

__global__ void k_build_csr(const int4* __restrict__ row4, const int4* __restrict__ col4) {
    int i = blockIdx.x * blockDim.x + threadIdx.x;
    if (i < N_EDGES / 4) {
        int4 r = __ldg(&row4[i]);
        int4 c = __ldg(&col4[i]);
        g_csr[atomicAdd(&g_cur[c.x], 1)] = r.x;
        g_csr[atomicAdd(&g_cur[c.y], 1)] = r.y;
        g_csr[atomicAdd(&g_cur[c.z], 1)] = r.z;
        g_csr[atomicAdd(&g_cur[c.w], 1)] = r.w;
    }
}

// ---------------------------------------------------------------------------
// Convert both weight matrices to fp16 (32k elements total).
__global__ void k_conv_w(const float* __restrict__ W1, const float* __restrict__ W2) {
    int i = blockIdx.x * blockDim.x + threadIdx.x;
    if (i < D * D) {
        g_w1[i] = __float2half_rn(W1[i]);
        g_w2[i] = __float2half_rn(W2[i]);
    }
}

// a[i,:] = fp16( x[i,:] * dinv[i] )  — pre-scaled GEMM input. Runs after k_scan.
__global__ void k_scale_x(const float* __restrict__ x) {
    int idx = blockIdx.x * blockDim.x + threadIdx.x;   // one float4 group
    if (idx >= N_NODES * (D / 4)) return;
    int node = idx >> 5;
    int c4   = (idx & 31) * 4;
    float di = g_dinv[node];
    float4 v = *(const float4*)&x[(size_t)node * D + c4];
    union { __half2 h2[2]; uint2 u; } pk;
    pk.h2[0] = __floats2half2_rn(v.x * di, v.y * di);
    pk.h2[1] = __floats2half2_rn(v.z * di, v.w * di);
    *(uint2*)&g_a[(size_t)node * D + c4] = pk.u;
}

// ---------------------------------------------------------------------------
// Tensor-core GEMM: out = A @ W, fp16 in, fp32 accum, fp16 out.
// Block = 64 rows x 128 cols, 8 warps in 2x4, warp tile 32x32 (2x2 frags).
// A rows are pre-scaled by dinv, so no epilogue scale. Buffers padded -> no guards.
__global__ void __launch_bounds__(256)
k_gemm_wmma(const __half* __restrict__ A, const __half* __restrict__ W,
            __half* __restrict__ out) {
    __shared__ float Cs[64][132];   // +4 pad

    const int wid = threadIdx.x >> 5;
    const int wr  = wid >> 2;        // 0..1
    const int wc  = wid & 3;         // 0..3
    const int row0 = blockIdx.x * 64 + wr * 32;
    const int col0 = wc * 32;

    wmma::fragment<wmma::accumulator, 16, 16, 16, float> acc[2][2];
#pragma unroll
    for (int i = 0; i < 2; i++)
#pragma unroll
        for (int j = 0; j < 2; j++) wmma::fill_fragment(acc[i][j], 0.0f);

#pragma unroll
    for (int k = 0; k < D; k += 16) {
        wmma::fragment<wmma::matrix_a, 16, 16, 16, __half, wmma::row_major> a0, a1;
        wmma::fragment<wmma::matrix_b, 16, 16, 16, __half, wmma::row_major> b0, b1;
        wmma::load_matrix_sync(a0, A + (size_t)row0 * D + k, D);
        wmma::load_matrix_sync(a1, A + (size_t)(row0 + 16) * D + k, D);
        wmma::load_matrix_sync(b0, W + (size_t)k * D + col0, D);
        wmma::load_matrix_sync(b1, W + (size_t)k * D + col0 + 16, D);
        wmma::mma_sync(acc[0][0], a0, b0, acc[0][0]);
        wmma::mma_sync(acc[0][1], a0, b1, acc[0][1]);
        wmma::mma_sync(acc[1][0], a1, b0, acc[1][0]);
        wmma::mma_sync(acc[1][1], a1, b1, acc[1][1]);
    }

#pragma unroll
    for (int i = 0; i < 2; i++)
#pragma unroll
        for (int j = 0; j < 2; j++)
            wmma::store_matrix_sync(&Cs[wr * 32 + i * 16][col0 + j * 16],
                                    acc[i][j], 132, wmma::mem_row_major);
    __syncthreads();

    // epilogue: fp32 smem -> fp16 global, coalesced
    const size_t outBase = (size_t)blockIdx.x * 64 * D;
    for (int g = threadIdx.x; g < 64 * 32; g += 256) {
        int r  = g >> 5;
        int c4 = (g & 31) * 4;
        float v0 = Cs[r][c4 + 0], v1 = Cs[r][c4 + 1];
        float v2 = Cs[r][c4 + 2], v3 = Cs[r][c4 + 3];
        union { __half2 h2[2]; uint2 u; } pk;
        pk.h2[0] = __floats2half2_rn(v0, v1);
        pk.h2[1] = __floats2half2_rn(v2, v3);
        *(uint2*)&out[outBase + (size_t)r * D + c4] = pk.u;
    }
}

// ---------------------------------------------------------------------------
__device__ __forceinline__ float4 ld_row4(const __half* __restrict__ xs, int r, int c4) {
    uint2 u = __ldg((const uint2*)(xs + (size_t)r * D + c4));
    __half2 h0 = *(__half2*)&u.x;
    __half2 h1 = *(__half2*)&u.y;
    float2 a0 = __half22float2(h0);
    float2 a1 = __half22float2(h1);
    return make_float4(a0.x, a0.y, a1.x, a1.y);
}

// Gather: one warp per node, fp32 accumulation over fp16 messages.
// r = prelu( dinv[c] * (xs[c] + sum_in xs[src]) + b , a )
// OUT_HALF: write fp16(r * dinv[c]) (pre-scaled input for next layer's GEMM)
// else:     write fp32 r (final output)
template <bool OUT_HALF>
__global__ void k_gather(const __half* __restrict__ xs, const float* __restrict__ b,
                         const float* __restrict__ a, float* __restrict__ outf,
                         __half* __restrict__ outh) {
    int node = (blockIdx.x * blockDim.x + threadIdx.x) >> 5;
    int lane = threadIdx.x & 31;
    if (node >= N_NODES) return;
    const int c4 = lane * 4;

    float4 acc = ld_row4(xs, node, c4);   // self loop

    int s = g_off[node];
    int e = g_off[node + 1];
    int i = s;
    for (; i + 4 <= e; i += 4) {
        int r0 = __ldg(&g_csr[i]);
        int r1 = __ldg(&g_csr[i + 1]);
        int r2 = __ldg(&g_csr[i + 2]);
        int r3 = __ldg(&g_csr[i + 3]);
        float4 v0 = ld_row4(xs, r0, c4);
        float4 v1 = ld_row4(xs, r1, c4);
        float4 v2 = ld_row4(xs, r2, c4);
        float4 v3 = ld_row4(xs, r3, c4);
        acc.x += (v0.x + v1.x) + (v2.x + v3.x);
        acc.y += (v0.y + v1.y) + (v2.y + v3.y);
        acc.z += (v0.z + v1.z) + (v2.z + v3.z);
        acc.w += (v0.w + v1.w) + (v2.w + v3.w);
    }
    for (; i < e; i++) {
        int r0 = __ldg(&g_csr[i]);
        float4 v0 = ld_row4(xs, r0, c4);
        acc.x += v0.x; acc.y += v0.y; acc.z += v0.z; acc.w += v0.w;
    }

    float  di = g_dinv[node];
    float4 bb = *(const float4*)&b[c4];
    float4 aa = *(const float4*)&a[c4];
    float4 o;
    o.x = fmaf(di, acc.x, bb.x); o.x = (o.x >= 0.f) ? o.x : aa.x * o.x;
    o.y = fmaf(di, acc.y, bb.y); o.y = (o.y >= 0.f) ? o.y : aa.y * o.y;
    o.z = fmaf(di, acc.z, bb.z); o.z = (o.z >= 0.f) ? o.z : aa.z * o.z;
    o.w = fmaf(di, acc.w, bb.w); o.w = (o.w >= 0.f) ? o.w : aa.w * o.w;

    if (OUT_HALF) {
        union { __half2 h2[2]; uint2 u; } pk;
        pk.h2[0] = __floats2half2_rn(o.x * di, o.y * di);
        pk.h2[1] = __floats2half2_rn(o.z * di, o.w * di);
        *(uint2*)&outh[(size_t)node * D + c4] = pk.u;
    } else {
        *(float4*)&outf[(size_t)node * D + c4] = o;
    }
}

// ---------------------------------------------------------------------------
extern "C" void kernel_launch(void* const* d_in, const int* in_sizes, int n_in,
                              void* d_out, int out_size) {
    const float* x  = (const float*)d_in[0];
    const int*   ei = (const int*)  d_in[1];
    const float* W1 = (const float*)d_in[2];
    const float* b1 = (const float*)d_in[3];
    const float* a1 = (const float*)d_in[4];
    const float* W2 = (const float*)d_in[5];
    const float* b2 = (const float*)d_in[6];
    const float* a2 = (const float*)d_in[7];
    float* out = (float*)d_out;

    const int4* row4 = (const int4*)ei;               // edge_index[0] = sources
    const int4* col4 = (const int4*)(ei + N_EDGES);   // edge_index[1] = targets

    __half *a_ptr, *xs_ptr, *w1_ptr, *w2_ptr;  int *deg_ptr;
    cudaGetSymbolAddress((void**)&a_ptr,   g_a);
    cudaGetSymbolAddress((void**)&xs_ptr,  g_xsh);
    cudaGetSymbolAddress((void**)&w1_ptr,  g_w1);
    cudaGetSymbolAddress((void**)&w2_ptr,  g_w2);
    cudaGetSymbolAddress((void**)&deg_ptr, g_deg);

    // CSR build (once; reused by both layers)
    cudaMemsetAsync(deg_ptr, 0, N_NODES * sizeof(int), 0);
    const int e4blocks = (N_EDGES / 4 + 255) / 256;
    k_hist     <<<e4blocks, 256>>>(col4);
    k_conv_w   <<<(D * D + 255) / 256, 256>>>(W1, W2);
    k_scan     <<<1, 1024>>>();
    k_build_csr<<<e4blocks, 256>>>(row4, col4);
    k_scale_x  <<<(N_NODES * (D / 4) + 255) / 256, 256>>>(x);

    const int gemm_blocks   = N_PAD / 64;   // 782
    const int gather_blocks = (N_NODES * 32 + 255) / 256;

    // layer 1
    k_gemm_wmma<<<gemm_blocks, 256>>>(a_ptr, w1_ptr, xs_ptr);
    k_gather<true> <<<gather_blocks, 256>>>(xs_ptr, b1, a1, nullptr, a_ptr);
    // layer 2
    k_gemm_wmma<<<gemm_blocks, 256>>>(a_ptr, w2_ptr, xs_ptr);
    k_gather<false><<<gather_blocks, 256>>>(xs_ptr, b2, a2, out, nullptr);
}

// round 12
// speedup vs baseline: 2.1611x; 1.8178x over previous
#include <cuda_runtime.h>
#include <cuda_fp16.h>
#include <mma.h>

using namespace nvcuda;

#define N_NODES 50000
#define N_EDGES 800000
#define D 128
#define N_PAD 50048              // 782 * 64, padded row count for guard-free GEMM
#define SCAN_BLK 196             // ceil(50000/256)

// ---- scratch (device globals; no allocation allowed) ----
__device__ __half g_a  [N_PAD * D];     // 12.8 MB: layer-2 GEMM input (pre-scaled by dinv)
__device__ __half g_xsh[N_PAD * D];     // 12.8 MB: GEMM output (messages)
__device__ __half g_w1 [D * D];
__device__ __half g_w2 [D * D];
__device__ float  g_dinv[N_NODES];
__device__ int    g_deg [N_NODES];
__device__ int    g_off [N_NODES + 1];
__device__ int    g_cur [N_NODES];
__device__ int    g_csr [N_EDGES];      // source node per incoming edge, grouped by target
__device__ int    g_bsum[SCAN_BLK];
__device__ int    g_boff[SCAN_BLK];

// ---------------------------------------------------------------------------
__global__ void k_hist(const int4* __restrict__ col4) {
    int i = blockIdx.x * blockDim.x + threadIdx.x;
    if (i < N_EDGES / 4) {
        int4 c = __ldg(&col4[i]);
        atomicAdd(&g_deg[c.x], 1);
        atomicAdd(&g_deg[c.y], 1);
        atomicAdd(&g_deg[c.z], 1);
        atomicAdd(&g_deg[c.w], 1);
    }
}

// --- parallel scan: block sums -> scan sums -> apply -------------------------
__global__ void k_bsum() {
    __shared__ int sh[256];
    int t = threadIdx.x;
    int i = blockIdx.x * 256 + t;
    sh[t] = (i < N_NODES) ? g_deg[i] : 0;
    __syncthreads();
#pragma unroll
    for (int d = 128; d > 0; d >>= 1) {
        if (t < d) sh[t] += sh[t + d];
        __syncthreads();
    }
    if (t == 0) g_bsum[blockIdx.x] = sh[0];
}

__global__ void k_scan_b() {        // 1 block, 256 threads, scan 196 block sums
    __shared__ int sh[256];
    int t = threadIdx.x;
    int v = (t < SCAN_BLK) ? g_bsum[t] : 0;
    sh[t] = v;
    __syncthreads();
    for (int d = 1; d < 256; d <<= 1) {
        int u = 0;
        if (t >= d) u = sh[t - d];
        __syncthreads();
        if (t >= d) sh[t] += u;
        __syncthreads();
    }
    if (t < SCAN_BLK) g_boff[t] = sh[t] - v;   // exclusive
}

__global__ void k_apply() {
    __shared__ int sh[256];
    int t = threadIdx.x;
    int i = blockIdx.x * 256 + t;
    int dg = (i < N_NODES) ? g_deg[i] : 0;
    sh[t] = dg;
    __syncthreads();
    for (int d = 1; d < 256; d <<= 1) {
        int u = 0;
        if (t >= d) u = sh[t - d];
        __syncthreads();
        if (t >= d) sh[t] += u;
        __syncthreads();
    }
    if (i < N_NODES) {
        int excl = sh[t] - dg + g_boff[blockIdx.x];
        g_off[i] = excl;
        g_cur[i] = excl;
        g_dinv[i] = rsqrtf((float)(dg + 1));   // +1 self loop -> always > 0
        if (i == N_NODES - 1) g_off[N_NODES] = excl + dg;
    }
}

__global__ void k_build_csr(const int4* __restrict__ row4, const int4* __restrict__ col4) {
    int i = blockIdx.x * blockDim.x + threadIdx.x;
    if (i < N_EDGES / 4) {
        int4 r = __ldg(&row4[i]);
        int4 c = __ldg(&col4[i]);
        g_csr[atomicAdd(&g_cur[c.x], 1)] = r.x;
        g_csr[atomicAdd(&g_cur[c.y], 1)] = r.y;
        g_csr[atomicAdd(&g_cur[c.z], 1)] = r.z;
        g_csr[atomicAdd(&g_cur[c.w], 1)] = r.w;
    }
}

// ---------------------------------------------------------------------------
__global__ void k_conv_w(const float* __restrict__ W1, const float* __restrict__ W2) {
    int i = blockIdx.x * blockDim.x + threadIdx.x;
    if (i < D * D) {
        g_w1[i] = __float2half_rn(W1[i]);
        g_w2[i] = __float2half_rn(W2[i]);
    }
}

// ---------------------------------------------------------------------------
// Tensor-core GEMM, fp16 input from global (layer 2): out = A @ W.
// Block = 64 rows x 128 cols, 8 warps 2x4, warp tile 32x32.
__global__ void __launch_bounds__(256)
k_gemm_wmma(const __half* __restrict__ A, const __half* __restrict__ W,
            __half* __restrict__ out) {
    __shared__ float Cs[64][132];

    const int wid = threadIdx.x >> 5;
    const int wr  = wid >> 2;
    const int wc  = wid & 3;
    const int row0 = blockIdx.x * 64 + wr * 32;
    const int col0 = wc * 32;

    wmma::fragment<wmma::accumulator, 16, 16, 16, float> acc[2][2];
#pragma unroll
    for (int i = 0; i < 2; i++)
#pragma unroll
        for (int j = 0; j < 2; j++) wmma::fill_fragment(acc[i][j], 0.0f);

#pragma unroll
    for (int k = 0; k < D; k += 16) {
        wmma::fragment<wmma::matrix_a, 16, 16, 16, __half, wmma::row_major> a0, a1;
        wmma::fragment<wmma::matrix_b, 16, 16, 16, __half, wmma::row_major> b0, b1;
        wmma::load_matrix_sync(a0, A + (size_t)row0 * D + k, D);
        wmma::load_matrix_sync(a1, A + (size_t)(row0 + 16) * D + k, D);
        wmma::load_matrix_sync(b0, W + (size_t)k * D + col0, D);
        wmma::load_matrix_sync(b1, W + (size_t)k * D + col0 + 16, D);
        wmma::mma_sync(acc[0][0], a0, b0, acc[0][0]);
        wmma::mma_sync(acc[0][1], a0, b1, acc[0][1]);
        wmma::mma_sync(acc[1][0], a1, b0, acc[1][0]);
        wmma::mma_sync(acc[1][1], a1, b1, acc[1][1]);
    }

#pragma unroll
    for (int i = 0; i < 2; i++)
#pragma unroll
        for (int j = 0; j < 2; j++)
            wmma::store_matrix_sync(&Cs[wr * 32 + i * 16][col0 + j * 16],
                                    acc[i][j], 132, wmma::mem_row_major);
    __syncthreads();

    const size_t outBase = (size_t)blockIdx.x * 64 * D;
    for (int g = threadIdx.x; g < 64 * 32; g += 256) {
        int r  = g >> 5;
        int c4 = (g & 31) * 4;
        union { __half2 h2[2]; uint2 u; } pk;
        pk.h2[0] = __floats2half2_rn(Cs[r][c4 + 0], Cs[r][c4 + 1]);
        pk.h2[1] = __floats2half2_rn(Cs[r][c4 + 2], Cs[r][c4 + 3]);
        *(uint2*)&out[outBase + (size_t)r * D + c4] = pk.u;
    }
}

// Layer-1 GEMM: fp32 A from the harness input, converted to fp16 in a guarded
// smem staging tile. As and Cs share one smem union (As dead after the k-loop;
// the __syncthreads() after the loop orders all As reads before any Cs write)
// -> peak static smem 33.8 KB, under the 48 KB limit.
__global__ void __launch_bounds__(256)
k_gemm_wmma_f32(const float* __restrict__ A, const __half* __restrict__ W,
                __half* __restrict__ out) {
    __shared__ union SmemU {
        __half As[64][136];   // 17408 B
        float  Cs[64][132];   // 33792 B
    } sm;

    const int tid = threadIdx.x;
    const int wid = tid >> 5;
    const int wr  = wid >> 2;
    const int wc  = wid & 3;
    const int rowBase = blockIdx.x * 64;
    const int col0 = wc * 32;

    // stage A: 64 rows x 128 fp32 -> fp16 smem. 8192 elems / 256 thr = 32 each.
    {
        int r  = tid >> 2;            // 0..63
        int c0 = (tid & 3) * 32;      // 0,32,64,96
        int grow = rowBase + r;
        if (grow < N_NODES) {
            const float* src = A + (size_t)grow * D + c0;
#pragma unroll
            for (int q = 0; q < 8; q++) {
                float4 v = *(const float4*)(src + q * 4);
                union { __half2 h2[2]; uint2 u; } pk;
                pk.h2[0] = __floats2half2_rn(v.x, v.y);
                pk.h2[1] = __floats2half2_rn(v.z, v.w);
                *(uint2*)&sm.As[r][c0 + q * 4] = pk.u;
            }
        } else {
            uint2 z = make_uint2(0, 0);
#pragma unroll
            for (int q = 0; q < 8; q++) *(uint2*)&sm.As[r][c0 + q * 4] = z;
        }
    }
    __syncthreads();

    wmma::fragment<wmma::accumulator, 16, 16, 16, float> acc[2][2];
#pragma unroll
    for (int i = 0; i < 2; i++)
#pragma unroll
        for (int j = 0; j < 2; j++) wmma::fill_fragment(acc[i][j], 0.0f);

#pragma unroll
    for (int k = 0; k < D; k += 16) {
        wmma::fragment<wmma::matrix_a, 16, 16, 16, __half, wmma::row_major> a0, a1;
        wmma::fragment<wmma::matrix_b, 16, 16, 16, __half, wmma::row_major> b0, b1;
        wmma::load_matrix_sync(a0, &sm.As[wr * 32][k], 136);
        wmma::load_matrix_sync(a1, &sm.As[wr * 32 + 16][k], 136);
        wmma::load_matrix_sync(b0, W + (size_t)k * D + col0, D);
        wmma::load_matrix_sync(b1, W + (size_t)k * D + col0 + 16, D);
        wmma::mma_sync(acc[0][0], a0, b0, acc[0][0]);
        wmma::mma_sync(acc[0][1], a0, b1, acc[0][1]);
        wmma::mma_sync(acc[1][0], a1, b0, acc[1][0]);
        wmma::mma_sync(acc[1][1], a1, b1, acc[1][1]);
    }
    __syncthreads();   // WAR fence: all As reads done before Cs overwrites the union

#pragma unroll
    for (int i = 0; i < 2; i++)
#pragma unroll
        for (int j = 0; j < 2; j++)
            wmma::store_matrix_sync(&sm.Cs[wr * 32 + i * 16][col0 + j * 16],
                                    acc[i][j], 132, wmma::mem_row_major);
    __syncthreads();

    const size_t outBase = (size_t)blockIdx.x * 64 * D;
    for (int g = tid; g < 64 * 32; g += 256) {
        int r  = g >> 5;
        int c4 = (g & 31) * 4;
        union { __half2 h2[2]; uint2 u; } pk;
        pk.h2[0] = __floats2half2_rn(sm.Cs[r][c4 + 0], sm.Cs[r][c4 + 1]);
        pk.h2[1] = __floats2half2_rn(sm.Cs[r][c4 + 2], sm.Cs[r][c4 + 3]);
        *(uint2*)&out[outBase + (size_t)r * D + c4] = pk.u;
    }
}

// ---------------------------------------------------------------------------
__device__ __forceinline__ float4 ld_row4(const __half* __restrict__ xs, int r, int c4) {
    uint2 u = __ldg((const uint2*)(xs + (size_t)r * D + c4));
    __half2 h0 = *(__half2*)&u.x;
    __half2 h1 = *(__half2*)&u.y;
    float2 a0 = __half22float2(h0);
    float2 a1 = __half22float2(h1);
    return make_float4(a0.x, a0.y, a1.x, a1.y);
}

// Gather: one warp per node, fp32 accumulation over fp16 messages.
// SRC_SCALE: messages are NOT pre-scaled; multiply each by dinv[src] here.
// OUT_HALF : write fp16(result * dinv[node]) as next layer's pre-scaled input.
template <bool SRC_SCALE, bool OUT_HALF>
__global__ void k_gather(const __half* __restrict__ xs, const float* __restrict__ b,
                         const float* __restrict__ a, float* __restrict__ outf,
                         __half* __restrict__ outh) {
    int node = (blockIdx.x * blockDim.x + threadIdx.x) >> 5;
    int lane = threadIdx.x & 31;
    if (node >= N_NODES) return;
    const int c4 = lane * 4;
    const float di = g_dinv[node];

    float4 self = ld_row4(xs, node, c4);
    float sw = SRC_SCALE ? di : 1.0f;
    float4 acc = make_float4(self.x * sw, self.y * sw, self.z * sw, self.w * sw);

    int s = g_off[node];
    int e = g_off[node + 1];
    int i = s;
    for (; i + 4 <= e; i += 4) {
        int r0 = __ldg(&g_csr[i]);
        int r1 = __ldg(&g_csr[i + 1]);
        int r2 = __ldg(&g_csr[i + 2]);
        int r3 = __ldg(&g_csr[i + 3]);
        float4 v0 = ld_row4(xs, r0, c4);
        float4 v1 = ld_row4(xs, r1, c4);
        float4 v2 = ld_row4(xs, r2, c4);
        float4 v3 = ld_row4(xs, r3, c4);
        if (SRC_SCALE) {
            float w0 = __ldg(&g_dinv[r0]);
            float w1 = __ldg(&g_dinv[r1]);
            float w2 = __ldg(&g_dinv[r2]);
            float w3 = __ldg(&g_dinv[r3]);
            acc.x = fmaf(v0.x, w0, fmaf(v1.x, w1, fmaf(v2.x, w2, fmaf(v3.x, w3, acc.x))));
            acc.y = fmaf(v0.y, w0, fmaf(v1.y, w1, fmaf(v2.y, w2, fmaf(v3.y, w3, acc.y))));
            acc.z = fmaf(v0.z, w0, fmaf(v1.z, w1, fmaf(v2.z, w2, fmaf(v3.z, w3, acc.z))));
            acc.w = fmaf(v0.w, w0, fmaf(v1.w, w1, fmaf(v2.w, w2, fmaf(v3.w, w3, acc.w))));
        } else {
            acc.x += (v0.x + v1.x) + (v2.x + v3.x);
            acc.y += (v0.y + v1.y) + (v2.y + v3.y);
            acc.z += (v0.z + v1.z) + (v2.z + v3.z);
            acc.w += (v0.w + v1.w) + (v2.w + v3.w);
        }
    }
    for (; i < e; i++) {
        int r0 = __ldg(&g_csr[i]);
        float4 v0 = ld_row4(xs, r0, c4);
        float w0 = SRC_SCALE ? __ldg(&g_dinv[r0]) : 1.0f;
        acc.x = fmaf(v0.x, w0, acc.x);
        acc.y = fmaf(v0.y, w0, acc.y);
        acc.z = fmaf(v0.z, w0, acc.z);
        acc.w = fmaf(v0.w, w0, acc.w);
    }

    float4 bb = *(const float4*)&b[c4];
    float4 aa = *(const float4*)&a[c4];
    float4 o;
    o.x = fmaf(di, acc.x, bb.x); o.x = (o.x >= 0.f) ? o.x : aa.x * o.x;
    o.y = fmaf(di, acc.y, bb.y); o.y = (o.y >= 0.f) ? o.y : aa.y * o.y;
    o.z = fmaf(di, acc.z, bb.z); o.z = (o.z >= 0.f) ? o.z : aa.z * o.z;
    o.w = fmaf(di, acc.w, bb.w); o.w = (o.w >= 0.f) ? o.w : aa.w * o.w;

    if (OUT_HALF) {
        union { __half2 h2[2]; uint2 u; } pk;
        pk.h2[0] = __floats2half2_rn(o.x * di, o.y * di);
        pk.h2[1] = __floats2half2_rn(o.z * di, o.w * di);
        *(uint2*)&outh[(size_t)node * D + c4] = pk.u;
    } else {
        *(float4*)&outf[(size_t)node * D + c4] = o;
    }
}

// ---------------------------------------------------------------------------
extern "C" void kernel_launch(void* const* d_in, const int* in_sizes, int n_in,
                              void* d_out, int out_size) {
    const float* x  = (const float*)d_in[0];
    const int*   ei = (const int*)  d_in[1];
    const float* W1 = (const float*)d_in[2];
    const float* b1 = (const float*)d_in[3];
    const float* a1 = (const float*)d_in[4];
    const float* W2 = (const float*)d_in[5];
    const float* b2 = (const float*)d_in[6];
    const float* a2 = (const float*)d_in[7];
    float* out = (float*)d_out;

    const int4* row4 = (const int4*)ei;               // edge_index[0] = sources
    const int4* col4 = (const int4*)(ei + N_EDGES);   // edge_index[1] = targets

    __half *a_ptr, *xs_ptr, *w1_ptr, *w2_ptr;  int *deg_ptr;
    cudaGetSymbolAddress((void**)&a_ptr,   g_a);
    cudaGetSymbolAddress((void**)&xs_ptr,  g_xsh);
    cudaGetSymbolAddress((void**)&w1_ptr,  g_w1);
    cudaGetSymbolAddress((void**)&w2_ptr,  g_w2);
    cudaGetSymbolAddress((void**)&deg_ptr, g_deg);

    // one-time stream/event setup (host resources only; no device allocations;
    // created on the first, uncaptured call — never during graph capture)
    static cudaStream_t s_side = nullptr;
    static cudaEvent_t  ev_fork = nullptr, ev_join = nullptr;
    if (s_side == nullptr)  cudaStreamCreateWithFlags(&s_side, cudaStreamNonBlocking);
    if (ev_fork == nullptr) cudaEventCreateWithFlags(&ev_fork, cudaEventDisableTiming);
    if (ev_join == nullptr) cudaEventCreateWithFlags(&ev_join, cudaEventDisableTiming);

    const int e4blocks     = (N_EDGES / 4 + 255) / 256;
    const int gemm_blocks  = N_PAD / 64;   // 782
    const int gather_blocks = (N_NODES * 32 + 255) / 256;

    // ---- fork: CSR chain on side stream (independent of GEMM-1) ----
    cudaEventRecord(ev_fork, 0);
    cudaStreamWaitEvent(s_side, ev_fork, 0);
    cudaMemsetAsync(deg_ptr, 0, N_NODES * sizeof(int), s_side);
    k_hist     <<<e4blocks, 256, 0, s_side>>>(col4);
    k_bsum     <<<SCAN_BLK, 256, 0, s_side>>>();
    k_scan_b   <<<1, 256, 0, s_side>>>();
    k_apply    <<<SCAN_BLK, 256, 0, s_side>>>();
    k_build_csr<<<e4blocks, 256, 0, s_side>>>(row4, col4);
    cudaEventRecord(ev_join, s_side);

    // ---- main stream: weight convert + layer-1 GEMM (no dinv needed) ----
    k_conv_w       <<<(D * D + 255) / 256, 256>>>(W1, W2);
    k_gemm_wmma_f32<<<gemm_blocks, 256>>>(x, w1_ptr, xs_ptr);

    // ---- join: gather-1 needs CSR + dinv + messages ----
    cudaStreamWaitEvent(0, ev_join, 0);
    k_gather<true, true>  <<<gather_blocks, 256>>>(xs_ptr, b1, a1, nullptr, a_ptr);

    // ---- layer 2 ----
    k_gemm_wmma<<<gemm_blocks, 256>>>(a_ptr, w2_ptr, xs_ptr);
    k_gather<false, false><<<gather_blocks, 256>>>(xs_ptr, b2, a2, out, nullptr);
}